// round 7
// baseline (speedup 1.0000x reference)
#include <cuda_runtime.h>
#include <cuda_bf16.h>
#include <math.h>
#include <stdint.h>

// ---------------------------------------------------------------------------
// SimpleVQ: B=32, H=1, L=4096, D=64, S=512
// out (f32): quantized[NVEC*64] | z[NVEC] | l_commit | errs2[NVEC]
// int8 dp4a distance pass + runtime-certified margin + exact fp32 refine.
// ---------------------------------------------------------------------------

typedef unsigned long long ull;

#define NVEC   131072
#define NCODE  512
#define ZOFF   8388608
#define LOFF   8519680
#define EOFF   8519681
#define NBLK   148
#define NTHR   512
#define NTILE  1024

#define CBS    80              // int8 codebook row stride (64 data + 16 pad)
#define DSTRIDE 272            // per-thread bf16 dist buffer stride (16-aligned)

// ---- smem layout (bytes) ---------------------------------------------------
#define SCB    0               // int8 codebook [512][80]        40960
#define SDIST  40960           // bf16 dists, per-thread 272B   139264
#define SCN    180224          // fp32 ||c||^2 [512]              2048
#define SMIN   182272          // u32 per-row approx min           512
#define SKEY   182784          // ull[128] final keys             1024
#define SRED   183808          // float[512]                      2048
#define SMEM_BYTES 185856

__device__ float         g_cbf[512 * 64];    // fp32 [s][d]
__device__ unsigned char g_cbi[512 * CBS];   // int8 [s][80]
__device__ float         g_cn[512];
__device__ float         g_part[NBLK];

// ---- helpers ---------------------------------------------------------------
__device__ __forceinline__ int dp4a(int a, int b, int c) {
    int r;
    asm("dp4a.s32.s32 %0, %1, %2, %3;" : "=r"(r) : "r"(a), "r"(b), "r"(c));
    return r;
}
__device__ __forceinline__ uint32_t bf2(float lo, float hi) {
    uint32_t r; asm("cvt.rn.bf16x2.f32 %0, %1, %2;" : "=r"(r) : "f"(hi), "f"(lo)); return r;
}
__device__ __forceinline__ uint32_t minbf2(uint32_t a, uint32_t b) {
    uint32_t r; asm("min.bf16x2 %0, %1, %2;" : "=r"(r) : "r"(a), "r"(b)); return r;
}
__device__ __forceinline__ uint32_t enc32(float f) {
    uint32_t u = __float_as_uint(f);
    return (u & 0x80000000u) ? ~u : (u | 0x80000000u);
}
__device__ __forceinline__ float dec32(uint32_t m) {
    uint32_t u = (m & 0x80000000u) ? (m & 0x7FFFFFFFu) : ~m;
    return __uint_as_float(u);
}

// ---------------------------------------------------------------------------
// Init: codebook (double trig; identical math to all passing rounds)
// ---------------------------------------------------------------------------
__global__ void vq_init() {
    __shared__ float red[64];
    const int s = blockIdx.x;
    const int d = threadIdx.x;
    const int j = d & 31;

    double expn = -((double)(2 * j) / 64.0);
    float  il   = (float)pow(100000.0, expn);
    float  pre  = __fmul_rn((float)s, il);
    float  e    = (d < 32) ? (float)sin((double)pre) : (float)cos((double)pre);

    red[d] = __fmul_rn(e, e);
    __syncthreads();
    for (int o = 32; o > 0; o >>= 1) {
        if (d < o) red[d] = __fadd_rn(red[d], red[d + o]);
        __syncthreads();
    }
    float m = __fadd_rn(__fmul_rn(red[0], (1.0f / 64.0f)), 1e-6f);
    __syncthreads();
    float r = (float)(1.0 / sqrt((double)m));
    float c = __fmul_rn(__fmul_rn(e, r), 0.35355339059327373f);

    g_cbf[s * 64 + d] = c;
    int q = __float2int_rn(fminf(fmaxf(__fmul_rn(c, 254.f), -127.f), 127.f));
    g_cbi[s * CBS + d] = (unsigned char)(q & 0xFF);
    if (d < 16) g_cbi[s * CBS + 64 + d] = 0;

    red[d] = __fmul_rn(c, c);
    __syncthreads();
    for (int o = 32; o > 0; o >>= 1) {
        if (d < o) red[d] = __fadd_rn(red[d], red[d + o]);
        __syncthreads();
    }
    if (d == 0) g_cn[s] = red[0];
}

// ---------------------------------------------------------------------------
__device__ __forceinline__ void refine(const float* __restrict__ vecs,
                                       int vglob, int row, int code,
                                       float vn, const float* scn, ull* skey) {
    const float4* vp = (const float4*)(vecs + ((size_t)vglob) * 64);
    const float4* cp = (const float4*)(g_cbf + (size_t)code * 64);
    float dot = 0.f;
#pragma unroll
    for (int kk = 0; kk < 16; kk++) {
        float4 a = vp[kk], b = cp[kk];
        dot = fmaf(a.x, b.x, dot);
        dot = fmaf(a.y, b.y, dot);
        dot = fmaf(a.z, b.z, dot);
        dot = fmaf(a.w, b.w, dot);
    }
    float dist = __fadd_rn(fmaf(-2.f, dot, vn), scn[code]);
    ull key = ((ull)enc32(dist) << 9) | (uint32_t)code;
    atomicMin(&skey[row], key);
}

// ---------------------------------------------------------------------------
__global__ void __launch_bounds__(NTHR, 1) vq_main(const float* __restrict__ vecs,
                                                   const float* __restrict__ mask,
                                                   float* __restrict__ out) {
    extern __shared__ unsigned char smem[];
    float*    scn  = (float*)(smem + SCN);
    uint32_t* smin = (uint32_t*)(smem + SMIN);
    ull*      skey = (ull*)(smem + SKEY);
    float*    sred = (float*)(smem + SRED);

    const int t   = threadIdx.x;
    const int row = t >> 2;
    const int seg = t & 3;

    // ---- load int8 codebook + cn into smem ----
    {
        uint4* dst = (uint4*)(smem + SCB);
        const uint4* src = (const uint4*)g_cbi;       // 2560 x 16B
        for (int i = t; i < (NCODE * CBS) / 16; i += NTHR) dst[i] = src[i];
        for (int i = t; i < NCODE; i += NTHR) scn[i] = g_cn[i];
    }
    __syncthreads();

    float lacc = 0.f;

    for (int tile = blockIdx.x; tile < NTILE; tile += NBLK) {
        const int vbase = tile * 128;
        const int vglob = vbase + row;

        // ---- load row: vn (exact ascending), maxabs, int8 quantize ----
        const float4* vp = (const float4*)(vecs + ((size_t)vglob) * 64);
        float vn = 0.f, ma = 0.f;
#pragma unroll
        for (int i = 0; i < 16; i++) {
            float4 x = vp[i];
            vn = __fadd_rn(vn, __fmul_rn(x.x, x.x));
            vn = __fadd_rn(vn, __fmul_rn(x.y, x.y));
            vn = __fadd_rn(vn, __fmul_rn(x.z, x.z));
            vn = __fadd_rn(vn, __fmul_rn(x.w, x.w));
            ma = fmaxf(ma, fmaxf(fmaxf(fabsf(x.x), fabsf(x.y)),
                                 fmaxf(fabsf(x.z), fabsf(x.w))));
        }
        const float inv = (ma > 0.f) ? (127.f / ma) : 0.f;
        const float sv  = ma * (1.f / 127.f);
        int qv[16];
#pragma unroll
        for (int i = 0; i < 16; i++) {
            float4 x = vp[i];
            int q0 = __float2int_rn(x.x * inv);
            int q1 = __float2int_rn(x.y * inv);
            int q2 = __float2int_rn(x.z * inv);
            int q3 = __float2int_rn(x.w * inv);
            qv[i] = (int)((uint32_t)(q0 & 0xFF) | ((uint32_t)(q1 & 0xFF) << 8)
                  | ((uint32_t)(q2 & 0xFF) << 16) | ((uint32_t)q3 << 24));
        }
        const float m2 = __fmul_rn(-2.f * (1.f / 254.f), sv);
        // certified margin: 2*(11.32*sv + (1/508)*8*sqrt(vn)) + bf16 store + slush
        const float margin = fmaf(22.7f, sv, fmaf(0.0320f, sqrtf(vn), 0.45f));

        if (t < 128) { smin[t] = 0xFFFFFFFFu; skey[t] = ~0ull; }
        __syncthreads();

        // ---- dp4a distance pass: this thread covers codes seg+4k, k=0..127 ----
        float localmin = 3.4e38f;
        float prevd = 0.f;
        const int4* cbp = (const int4*)(smem + SCB + seg * CBS);
        uint32_t* dbuf = (uint32_t*)(smem + SDIST + t * DSTRIDE);
#pragma unroll 4
        for (int k = 0; k < 128; k++) {
            int4 c0 = cbp[0], c1 = cbp[1], c2 = cbp[2], c3 = cbp[3];
            cbp += 20;   // 4 codes * 80B = 320B = 20 int4
            int id = 0;
            id = dp4a(qv[0],  c0.x, id); id = dp4a(qv[1],  c0.y, id);
            id = dp4a(qv[2],  c0.z, id); id = dp4a(qv[3],  c0.w, id);
            id = dp4a(qv[4],  c1.x, id); id = dp4a(qv[5],  c1.y, id);
            id = dp4a(qv[6],  c1.z, id); id = dp4a(qv[7],  c1.w, id);
            id = dp4a(qv[8],  c2.x, id); id = dp4a(qv[9],  c2.y, id);
            id = dp4a(qv[10], c2.z, id); id = dp4a(qv[11], c2.w, id);
            id = dp4a(qv[12], c3.x, id); id = dp4a(qv[13], c3.y, id);
            id = dp4a(qv[14], c3.z, id); id = dp4a(qv[15], c3.w, id);
            const int code = 4 * k + seg;
            float dist = fmaf(m2, (float)id, __fadd_rn(vn, scn[code]));
            localmin = fminf(localmin, dist);
            if (k & 1) dbuf[k >> 1] = bf2(prevd, dist);
            else       prevd = dist;
        }
        atomicMin(&smin[row], enc32(localmin));
        __syncthreads();

        // ---- threshold scan + exact fp32 refine ----
        {
            const float thr = dec32(smin[row]) + margin;
            const uint4* db = (const uint4*)(smem + SDIST + t * DSTRIDE);
#pragma unroll 1
            for (int i = 0; i < 16; i++) {
                uint4 w = db[i];
                uint32_t mm = minbf2(minbf2(w.x, w.y), minbf2(w.z, w.w));
                float f1 = __uint_as_float(mm << 16);
                float f2 = __uint_as_float(mm & 0xFFFF0000u);
                if (fminf(f1, f2) < thr) {
                    uint32_t ws[4] = {w.x, w.y, w.z, w.w};
#pragma unroll
                    for (int m = 0; m < 4; m++) {
                        float flo = __uint_as_float(ws[m] << 16);
                        float fhi = __uint_as_float(ws[m] & 0xFFFF0000u);
                        if (flo < thr)
                            refine(vecs, vglob, row, 4 * (8 * i + 2 * m) + seg, vn, scn, skey);
                        if (fhi < thr)
                            refine(vecs, vglob, row, 4 * (8 * i + 2 * m + 1) + seg, vn, scn, skey);
                    }
                }
            }
        }
        __syncthreads();

        // ---- outputs ----
        if (t < 128) {
            ull key = skey[t];
            int s = (int)(key & 511);
            float dist = dec32((uint32_t)(key >> 9));
            float er = fmaxf(dist, 0.f);
            int v = vbase + t;
            out[ZOFF + v] = (float)s;
            out[EOFF + v] = er;
            lacc = __fadd_rn(lacc, __fmul_rn(mask[v], er));
        }
        {
            int s = (int)(skey[row] & 511);
            const float4* cp = (const float4*)(g_cbf + (size_t)s * 64 + seg * 16);
            float4* dst = (float4*)(out + ((size_t)vglob) * 64 + seg * 16);
            dst[0] = cp[0]; dst[1] = cp[1]; dst[2] = cp[2]; dst[3] = cp[3];
        }
        __syncthreads();
    }

    // ---- l_commit block partial ----
    sred[t] = lacc;
    __syncthreads();
    for (int o = NTHR / 2; o > 0; o >>= 1) {
        if (t < o) sred[t] = __fadd_rn(sred[t], sred[t + o]);
        __syncthreads();
    }
    if (t == 0) g_part[blockIdx.x] = sred[0];
}

// ---------------------------------------------------------------------------
__global__ void vq_final(float* __restrict__ out) {
    __shared__ float s[256];
    int t = threadIdx.x;
    s[t] = (t < NBLK) ? g_part[t] : 0.f;
    __syncthreads();
    for (int o = 128; o > 0; o >>= 1) {
        if (t < o) s[t] = __fadd_rn(s[t], s[t + o]);
        __syncthreads();
    }
    if (t == 0) out[LOFF] = __fmul_rn(s[0], (1.0f / 131072.0f));
}

// ---------------------------------------------------------------------------
extern "C" void kernel_launch(void* const* d_in, const int* in_sizes, int n_in,
                              void* d_out, int out_size) {
    (void)in_sizes; (void)n_in; (void)out_size;
    const float* vecs = (const float*)d_in[0];
    const float* mask = (const float*)d_in[1];
    float* out = (float*)d_out;

    cudaFuncSetAttribute(vq_main, cudaFuncAttributeMaxDynamicSharedMemorySize, SMEM_BYTES);

    vq_init<<<NCODE, 64>>>();
    vq_main<<<NBLK, NTHR, SMEM_BYTES>>>(vecs, mask, out);
    vq_final<<<1, 256>>>(out);
}